// round 1
// baseline (speedup 1.0000x reference)
#include <cuda_runtime.h>

namespace {
constexpr int   S2      = 100;            // 10*10 grid cells
constexpr int   BATCH   = 32768;
constexpr int   CELLS   = BATCH * S2;     // 3,276,800
constexpr float SCALE   = 6.5131f / 40.0f;
constexpr int   THREADS = 256;
constexpr int   BLOCKS  = 2048;
}

// Scratch accumulators (no device mallocs allowed): xy, wh, obj, noobj, class
__device__ double g_acc[5];

__global__ void zero_acc_kernel() {
    if (threadIdx.x < 5) g_acc[threadIdx.x] = 0.0;
}

__device__ __forceinline__ float warp_sum(float v) {
#pragma unroll
    for (int o = 16; o > 0; o >>= 1)
        v += __shfl_down_sync(0xffffffffu, v, o);
    return v;
}

__global__ __launch_bounds__(THREADS) void loss_kernel(
    const float4* __restrict__ pred4,   // CELLS * 6 float4
    const float4* __restrict__ tgt4)    // CELLS float4
{
    float s_xy = 0.f, s_wh = 0.f, s_obj = 0.f, s_no = 0.f, s_cl = 0.f;
    const float inv_scale = 1.0f / SCALE;

    for (int i = blockIdx.x * THREADS + threadIdx.x; i < CELLS;
         i += BLOCKS * THREADS) {
        float4 t = __ldg(&tgt4[i]);
        const float4* p = pred4 + (size_t)i * 6;
        float4 p0 = __ldg(p + 0);
        float4 p1 = __ldg(p + 1);
        float4 p2 = __ldg(p + 2);
        float4 p3 = __ldg(p + 3);
        float4 p4 = __ldg(p + 4);
        float4 p5 = __ldg(p + 5);

        bool  coord = t.z > 0.0f;
        float cf = coord ? 1.0f : 0.0f;
        float nf = 1.0f - cf;

        // sigmoids via MUFU exp
        float sig_x = 1.0f / (1.0f + __expf(-p0.x));
        float sig_c = 1.0f / (1.0f + __expf(-p0.z));

        float dx = sig_x - t.x;
        s_xy += cf * dx * dx;

        float wt = coord ? t.y : 1.0f;
        float dw = p0.y - __logf(wt * inv_scale);
        s_wh += cf * dw * dw;

        float dob = sig_c - t.z;      // conf_t == 1 on coord cells
        s_obj += cf * dob * dob;
        s_no  += nf * sig_c * sig_c;  // conf_t == 0 on noobj cells

        // softmax-weighted mass over 21 logits (no max-sub: logits ~N(0,1))
        float lg[21] = {p0.w,
                        p1.x, p1.y, p1.z, p1.w,
                        p2.x, p2.y, p2.z, p2.w,
                        p3.x, p3.y, p3.z, p3.w,
                        p4.x, p4.y, p4.z, p4.w,
                        p5.x, p5.y, p5.z, p5.w};
        float se = 0.0f, sw = 0.0f;
#pragma unroll
        for (int c = 0; c < 21; c++) {
            float e = __expf(lg[c]);
            se += e;
            sw = fmaf(e, 1.0f + 0.5f * (float)c, sw);
        }
        float pm = sw / se;

        float mc   = (coord && t.w > 0.0f) ? 1.0f : 0.0f;
        float diff = 10.0f * (pm + 1.0f) / (t.w + 1.0f) - 10.0f;
        float ad   = fabsf(diff);
        float sl1  = (ad < 1.0f) ? 0.5f * diff * diff : (ad - 0.5f);
        s_cl += mc * sl1;
    }

    // intra-warp then intra-block reduction
    s_xy = warp_sum(s_xy);
    s_wh = warp_sum(s_wh);
    s_obj = warp_sum(s_obj);
    s_no = warp_sum(s_no);
    s_cl = warp_sum(s_cl);

    __shared__ float sm[5][THREADS / 32];
    int lane = threadIdx.x & 31;
    int warp = threadIdx.x >> 5;
    if (lane == 0) {
        sm[0][warp] = s_xy;
        sm[1][warp] = s_wh;
        sm[2][warp] = s_obj;
        sm[3][warp] = s_no;
        sm[4][warp] = s_cl;
    }
    __syncthreads();
    if (warp == 0) {
        float v0 = (lane < THREADS / 32) ? sm[0][lane] : 0.f;
        float v1 = (lane < THREADS / 32) ? sm[1][lane] : 0.f;
        float v2 = (lane < THREADS / 32) ? sm[2][lane] : 0.f;
        float v3 = (lane < THREADS / 32) ? sm[3][lane] : 0.f;
        float v4 = (lane < THREADS / 32) ? sm[4][lane] : 0.f;
        v0 = warp_sum(v0);
        v1 = warp_sum(v1);
        v2 = warp_sum(v2);
        v3 = warp_sum(v3);
        v4 = warp_sum(v4);
        if (lane == 0) {
            atomicAdd(&g_acc[0], (double)v0);
            atomicAdd(&g_acc[1], (double)v1);
            atomicAdd(&g_acc[2], (double)v2);
            atomicAdd(&g_acc[3], (double)v3);
            atomicAdd(&g_acc[4], (double)v4);
        }
    }
}

__global__ void finalize_kernel(float* __restrict__ out) {
    if (threadIdx.x == 0) {
        double xy = g_acc[0], wh = g_acc[1], obj = g_acc[2];
        double no = g_acc[3], cl = g_acc[4];
        double total = 10.0 * (xy + wh) + obj + 1.0 * no + 0.5 * cl;
        double inv_bs = 1.0 / (double)BATCH;
        out[0] = (float)(xy * inv_bs);
        out[1] = (float)(wh * inv_bs);
        out[2] = (float)(obj * inv_bs);
        out[3] = (float)(no * inv_bs);
        out[4] = (float)(cl * inv_bs);
        out[5] = (float)(total * inv_bs);
    }
}

extern "C" void kernel_launch(void* const* d_in, const int* in_sizes, int n_in,
                              void* d_out, int out_size) {
    const float4* pred4 = (const float4*)d_in[0];  // pred_tensor  [32768,10,10,24] f32
    const float4* tgt4  = (const float4*)d_in[1];  // target_tensor[32768,10,10,4]  f32
    float* out = (float*)d_out;                    // 6 x f32

    zero_acc_kernel<<<1, 32>>>();
    loss_kernel<<<BLOCKS, THREADS>>>(pred4, tgt4);
    finalize_kernel<<<1, 32>>>(out);
}